// round 2
// baseline (speedup 1.0000x reference)
#include <cuda_runtime.h>
#include <math.h>

// Problem constants
#define TOKENS   8192      // B*S = 4*2048
#define HDIM     512
#define FDIM     2048
#define EDIM     8
#define KSEL     2
#define NPAIRS   (TOKENS*KSEL)   // 16384

// ----- scratch (device globals: allocation-free per harness rules) -----
__device__ int   g_counts[EDIM];
__device__ int   g_offsets[EDIM];
__device__ int   g_cursor[EDIM];
__device__ int   g_pair_tok[NPAIRS];
__device__ float g_pair_w[NPAIRS];
__device__ int   g_topk_e[NPAIRS];
__device__ float g_topk_w[NPAIRS];
__device__ float g_act[(size_t)NPAIRS * FDIM];   // 128 MB fp32 activations

// ---------------------------------------------------------------------
// Zero output accumulator + counters (runs every replay; out is poisoned)
// ---------------------------------------------------------------------
__global__ void zero_kernel(float* __restrict__ out) {
    int i = blockIdx.x * blockDim.x + threadIdx.x;
    float4* o4 = (float4*)out;
    const int n4 = TOKENS * HDIM / 4;
    float4 z = make_float4(0.f, 0.f, 0.f, 0.f);
    for (int j = i; j < n4; j += gridDim.x * blockDim.x) o4[j] = z;
    if (blockIdx.x == 0 && threadIdx.x < EDIM) {
        g_counts[threadIdx.x] = 0;
        g_cursor[threadIdx.x] = 0;
    }
}

// ---------------------------------------------------------------------
// Router: logits -> softmax -> probs out, top-2 (jax tie-break), gates.
// One warp per token.
// ---------------------------------------------------------------------
__global__ void router_kernel(const float* __restrict__ x,
                              const float* __restrict__ rw,
                              float* __restrict__ probs_out,
                              float* __restrict__ topk_out) {
    __shared__ float s_rw[EDIM * HDIM];   // 16 KB
    for (int i = threadIdx.x; i < EDIM * HDIM; i += blockDim.x) s_rw[i] = rw[i];
    __syncthreads();

    const int warp = threadIdx.x >> 5;
    const int lane = threadIdx.x & 31;
    const int t = blockIdx.x * 8 + warp;
    if (t >= TOKENS) return;

    const float* xr = x + t * HDIM;
    float acc[EDIM];
#pragma unroll
    for (int e = 0; e < EDIM; e++) acc[e] = 0.f;

    for (int h = lane; h < HDIM; h += 32) {
        float v = xr[h];
#pragma unroll
        for (int e = 0; e < EDIM; e++) acc[e] = fmaf(v, s_rw[e * HDIM + h], acc[e]);
    }
#pragma unroll
    for (int e = 0; e < EDIM; e++) {
#pragma unroll
        for (int off = 16; off > 0; off >>= 1)
            acc[e] += __shfl_xor_sync(0xffffffff, acc[e], off);
    }
    if (lane == 0) {
        float mx = acc[0];
#pragma unroll
        for (int e = 1; e < EDIM; e++) mx = fmaxf(mx, acc[e]);
        float p[EDIM];
        float s = 0.f;
#pragma unroll
        for (int e = 0; e < EDIM; e++) { p[e] = expf(acc[e] - mx); s += p[e]; }
        float inv = 1.f / s;
#pragma unroll
        for (int e = 0; e < EDIM; e++) { p[e] *= inv; probs_out[t * EDIM + e] = p[e]; }

        // top-1: strict > with ascending scan keeps FIRST max (jax tie-break)
        int i1 = 0; float p1 = p[0];
#pragma unroll
        for (int e = 1; e < EDIM; e++) if (p[e] > p1) { p1 = p[e]; i1 = e; }
        int i2 = -1; float p2 = -1.f;
#pragma unroll
        for (int e = 0; e < EDIM; e++) if (e != i1 && p[e] > p2) { p2 = p[e]; i2 = e; }

        float wsum = p1 + p2 + 1e-9f;
        float w1 = p1 / wsum, w2 = p2 / wsum;

        topk_out[t * 2 + 0] = (float)i1;
        topk_out[t * 2 + 1] = (float)i2;
        g_topk_e[t * 2 + 0] = i1;  g_topk_e[t * 2 + 1] = i2;
        g_topk_w[t * 2 + 0] = w1;  g_topk_w[t * 2 + 1] = w2;
        atomicAdd(&g_counts[i1], 1);
        atomicAdd(&g_counts[i2], 1);
    }
}

// ---------------------------------------------------------------------
__global__ void offsets_kernel() {
    if (threadIdx.x == 0) {
        int off = 0;
#pragma unroll
        for (int e = 0; e < EDIM; e++) { g_offsets[e] = off; off += g_counts[e]; }
    }
}

__global__ void scatter_kernel() {
    int t = blockIdx.x * blockDim.x + threadIdx.x;
    if (t >= TOKENS) return;
#pragma unroll
    for (int k = 0; k < KSEL; k++) {
        int e = g_topk_e[t * 2 + k];
        int pos = atomicAdd(&g_cursor[e], 1);
        int idx = g_offsets[e] + pos;
        g_pair_tok[idx] = t;
        g_pair_w[idx] = g_topk_w[t * 2 + k];
    }
}

// ---------------------------------------------------------------------
// Shared GEMM mainloop machinery: 128x128 tile, BK=16, 8x8 per thread,
// NT layout (both operands K-contiguous), double-buffered smem with
// register-staged prefetch (one __syncthreads per K-tile; LDG latency
// hidden under the 16x64-FMA compute block).
// ---------------------------------------------------------------------
#define STORE_TILE(As, Bs, kb, row) do {                                   \
    As[(kb + 0) * 128 + row] = av0.x;  As[(kb + 1) * 128 + row] = av0.y;   \
    As[(kb + 2) * 128 + row] = av0.z;  As[(kb + 3) * 128 + row] = av0.w;   \
    As[(kb + 4) * 128 + row] = av1.x;  As[(kb + 5) * 128 + row] = av1.y;   \
    As[(kb + 6) * 128 + row] = av1.z;  As[(kb + 7) * 128 + row] = av1.w;   \
    Bs[(kb + 0) * 128 + row] = bv0.x;  Bs[(kb + 1) * 128 + row] = bv0.y;   \
    Bs[(kb + 2) * 128 + row] = bv0.z;  Bs[(kb + 3) * 128 + row] = bv0.w;   \
    Bs[(kb + 4) * 128 + row] = bv1.x;  Bs[(kb + 5) * 128 + row] = bv1.y;   \
    Bs[(kb + 6) * 128 + row] = bv1.z;  Bs[(kb + 7) * 128 + row] = bv1.w;   \
} while (0)

#define COMPUTE_TILE(As, Bs) do {                                          \
    _Pragma("unroll")                                                      \
    for (int kk = 0; kk < 16; kk++) {                                      \
        float4 a0 = *(const float4*)(As + kk * 128 + ty * 8);              \
        float4 a1 = *(const float4*)(As + kk * 128 + ty * 8 + 4);          \
        float4 b0 = *(const float4*)(Bs + kk * 128 + tx * 8);              \
        float4 b1 = *(const float4*)(Bs + kk * 128 + tx * 8 + 4);          \
        float ar[8] = {a0.x, a0.y, a0.z, a0.w, a1.x, a1.y, a1.z, a1.w};    \
        float br[8] = {b0.x, b0.y, b0.z, b0.w, b1.x, b1.y, b1.z, b1.w};    \
        _Pragma("unroll")                                                  \
        for (int i = 0; i < 8; i++)                                        \
            _Pragma("unroll")                                              \
            for (int j = 0; j < 8; j++)                                    \
                c[i][j] = fmaf(ar[i], br[j], c[i][j]);                     \
    }                                                                      \
} while (0)

// ---------------------------------------------------------------------
// GEMM1: act[p, f] = GELU( x[tok(p), :] . fc1_w[e, f, :] + fc1_b[e, f] )
// grid: (FDIM/128, TOKENS/128, EDIM); empty tiles early-exit.
// ---------------------------------------------------------------------
__global__ __launch_bounds__(256, 2)
void gemm1_kernel(const float* __restrict__ x,
                  const float* __restrict__ fc1_w,
                  const float* __restrict__ fc1_b) {
    const int e = blockIdx.z;
    const int count = g_counts[e];
    const int mt = blockIdx.y;
    if (mt * 128 >= count) return;
    const int base = g_offsets[e];
    const int ft = blockIdx.x;

    __shared__ float As[2][16 * 128];   // 16 KB x2
    __shared__ float Bs[2][16 * 128];   // 16 KB x2

    const int tid = threadIdx.x;
    const int row = tid >> 1;            // 0..127
    const int kb  = (tid & 1) * 8;       // k sub-offset: 0 or 8
    const int tx = tid & 15;             // n-dir
    const int ty = tid >> 4;             // m-dir

    const int m_g = mt * 128 + row;
    const int tok = (m_g < count) ? g_pair_tok[base + m_g] : 0;
    const float* aptr = x + tok * HDIM + kb;
    const float* bptr = fc1_w + (size_t)(e * FDIM + ft * 128 + row) * HDIM + kb;

    float c[8][8];
#pragma unroll
    for (int i = 0; i < 8; i++)
#pragma unroll
        for (int j = 0; j < 8; j++) c[i][j] = 0.f;

    // prologue: load k-tile 0
    float4 av0 = *(const float4*)(aptr);
    float4 av1 = *(const float4*)(aptr + 4);
    float4 bv0 = *(const float4*)(bptr);
    float4 bv1 = *(const float4*)(bptr + 4);

    int buf = 0;
    for (int k0 = 0; k0 < HDIM; k0 += 16) {
        STORE_TILE(As[buf], Bs[buf], kb, row);
        __syncthreads();
        if (k0 + 16 < HDIM) {           // prefetch next k-tile (overlaps compute)
            av0 = *(const float4*)(aptr + k0 + 16);
            av1 = *(const float4*)(aptr + k0 + 20);
            bv0 = *(const float4*)(bptr + k0 + 16);
            bv1 = *(const float4*)(bptr + k0 + 20);
        }
        COMPUTE_TILE(As[buf], Bs[buf]);
        buf ^= 1;
    }

    const int fbase = ft * 128 + tx * 8;
#pragma unroll
    for (int i = 0; i < 8; i++) {
        int m = mt * 128 + ty * 8 + i;
        if (m >= count) continue;
        float* dst = g_act + (size_t)(base + m) * FDIM + fbase;
#pragma unroll
        for (int j = 0; j < 8; j++) {
            float v = c[i][j] + fc1_b[e * FDIM + fbase + j];
            v = 0.5f * v * (1.0f + erff(v * 0.70710678118654752440f));  // exact GELU
            dst[j] = v;
        }
    }
}

// ---------------------------------------------------------------------
// GEMM2: out[tok, h] += w * ( act[p, :] . fc2_w[e, h, :] + fc2_b[e, h] )
// grid: (HDIM/128, TOKENS/128, EDIM)
// ---------------------------------------------------------------------
__global__ __launch_bounds__(256, 2)
void gemm2_kernel(const float* __restrict__ fc2_w,
                  const float* __restrict__ fc2_b,
                  float* __restrict__ out) {
    const int e = blockIdx.z;
    const int count = g_counts[e];
    const int mt = blockIdx.y;
    if (mt * 128 >= count) return;
    const int base = g_offsets[e];
    const int ht = blockIdx.x;

    __shared__ float As[2][16 * 128];
    __shared__ float Bs[2][16 * 128];

    const int tid = threadIdx.x;
    const int row = tid >> 1;
    const int kb  = (tid & 1) * 8;
    const int tx = tid & 15;
    const int ty = tid >> 4;

    const int m_g = mt * 128 + row;
    const int pa = (m_g < count) ? (base + m_g) : base;   // clamp: avoid OOB on g_act
    const float* aptr = g_act + (size_t)pa * FDIM + kb;
    const float* bptr = fc2_w + (size_t)(e * HDIM + ht * 128 + row) * FDIM + kb;

    float c[8][8];
#pragma unroll
    for (int i = 0; i < 8; i++)
#pragma unroll
        for (int j = 0; j < 8; j++) c[i][j] = 0.f;

    float4 av0 = *(const float4*)(aptr);
    float4 av1 = *(const float4*)(aptr + 4);
    float4 bv0 = *(const float4*)(bptr);
    float4 bv1 = *(const float4*)(bptr + 4);

    int buf = 0;
    for (int k0 = 0; k0 < FDIM; k0 += 16) {
        STORE_TILE(As[buf], Bs[buf], kb, row);
        __syncthreads();
        if (k0 + 16 < FDIM) {
            av0 = *(const float4*)(aptr + k0 + 16);
            av1 = *(const float4*)(aptr + k0 + 20);
            bv0 = *(const float4*)(bptr + k0 + 16);
            bv1 = *(const float4*)(bptr + k0 + 20);
        }
        COMPUTE_TILE(As[buf], Bs[buf]);
        buf ^= 1;
    }

    const int hbase = ht * 128 + tx * 8;
#pragma unroll
    for (int i = 0; i < 8; i++) {
        int m = mt * 128 + ty * 8 + i;
        if (m >= count) continue;
        int p = base + m;
        int tok = g_pair_tok[p];
        float w = g_pair_w[p];
        float* dst = out + tok * HDIM + hbase;
#pragma unroll
        for (int j = 0; j < 8; j++) {
            float y = c[i][j] + fc2_b[e * HDIM + hbase + j];
            atomicAdd(&dst[j], w * y);   // exactly 2 adds/elem; fp add commutative -> deterministic
        }
    }
}

// ---------------------------------------------------------------------
extern "C" void kernel_launch(void* const* d_in, const int* in_sizes, int n_in,
                              void* d_out, int out_size) {
    (void)in_sizes; (void)n_in; (void)out_size;
    const float* x        = (const float*)d_in[0];
    const float* router_w = (const float*)d_in[1];
    const float* fc1_w    = (const float*)d_in[2];
    const float* fc1_b    = (const float*)d_in[3];
    const float* fc2_w    = (const float*)d_in[4];
    const float* fc2_b    = (const float*)d_in[5];

    float* out   = (float*)d_out;                 // [TOKENS, HDIM]
    float* probs = out + TOKENS * HDIM;           // [TOKENS, EDIM]
    float* topk  = probs + TOKENS * EDIM;         // [TOKENS, KSEL] (indices as float)

    zero_kernel<<<1024, 256>>>(out);
    router_kernel<<<TOKENS / 8, 256>>>(x, router_w, probs, topk);
    offsets_kernel<<<1, 32>>>();
    scatter_kernel<<<TOKENS / 256, 256>>>();

    dim3 g1(FDIM / 128, TOKENS / 128, EDIM);      // (16, 64, 8)
    gemm1_kernel<<<g1, 256>>>(x, fc1_w, fc1_b);

    dim3 g2(HDIM / 128, TOKENS / 128, EDIM);      // (4, 64, 8)
    gemm2_kernel<<<g2, 256>>>(fc2_w, fc2_b, out);
}

// round 5
// speedup vs baseline: 1.0010x; 1.0010x over previous
#include <cuda_runtime.h>
#include <math.h>
#include <stdint.h>

// Problem constants
#define TOKENS   8192      // B*S = 4*2048
#define HDIM     512
#define FDIM     2048
#define EDIM     8
#define KSEL     2
#define NPAIRS   (TOKENS*KSEL)   // 16384

// ----- scratch (device globals: allocation-free per harness rules) -----
__device__ int   g_counts[EDIM];
__device__ int   g_offsets[EDIM];
__device__ int   g_cursor[EDIM];
__device__ int   g_pair_tok[NPAIRS];
__device__ float g_pair_w[NPAIRS];
__device__ int   g_topk_e[NPAIRS];
__device__ float g_topk_w[NPAIRS];
__device__ float g_act[(size_t)NPAIRS * FDIM];   // 128 MB fp32 activations

// ---------------------------------------------------------------------
// Zero output accumulator + counters (runs every replay; out is poisoned)
// ---------------------------------------------------------------------
__global__ void zero_kernel(float* __restrict__ out) {
    int i = blockIdx.x * blockDim.x + threadIdx.x;
    float4* o4 = (float4*)out;
    const int n4 = TOKENS * HDIM / 4;
    float4 z = make_float4(0.f, 0.f, 0.f, 0.f);
    for (int j = i; j < n4; j += gridDim.x * blockDim.x) o4[j] = z;
    if (blockIdx.x == 0 && threadIdx.x < EDIM) {
        g_counts[threadIdx.x] = 0;
        g_cursor[threadIdx.x] = 0;
    }
}

// ---------------------------------------------------------------------
// Router: logits -> softmax -> probs out, top-2 (jax tie-break), gates.
// One warp per token.
// ---------------------------------------------------------------------
__global__ void router_kernel(const float* __restrict__ x,
                              const float* __restrict__ rw,
                              float* __restrict__ probs_out,
                              float* __restrict__ topk_out) {
    __shared__ float s_rw[EDIM * HDIM];   // 16 KB
    for (int i = threadIdx.x; i < EDIM * HDIM; i += blockDim.x) s_rw[i] = rw[i];
    __syncthreads();

    const int warp = threadIdx.x >> 5;
    const int lane = threadIdx.x & 31;
    const int t = blockIdx.x * 8 + warp;
    if (t >= TOKENS) return;

    const float* xr = x + t * HDIM;
    float acc[EDIM];
#pragma unroll
    for (int e = 0; e < EDIM; e++) acc[e] = 0.f;

    for (int h = lane; h < HDIM; h += 32) {
        float v = xr[h];
#pragma unroll
        for (int e = 0; e < EDIM; e++) acc[e] = fmaf(v, s_rw[e * HDIM + h], acc[e]);
    }
#pragma unroll
    for (int e = 0; e < EDIM; e++) {
#pragma unroll
        for (int off = 16; off > 0; off >>= 1)
            acc[e] += __shfl_xor_sync(0xffffffff, acc[e], off);
    }
    if (lane == 0) {
        float mx = acc[0];
#pragma unroll
        for (int e = 1; e < EDIM; e++) mx = fmaxf(mx, acc[e]);
        float p[EDIM];
        float s = 0.f;
#pragma unroll
        for (int e = 0; e < EDIM; e++) { p[e] = expf(acc[e] - mx); s += p[e]; }
        float inv = 1.f / s;
#pragma unroll
        for (int e = 0; e < EDIM; e++) { p[e] *= inv; probs_out[t * EDIM + e] = p[e]; }

        // top-1: strict > with ascending scan keeps FIRST max (jax tie-break)
        int i1 = 0; float p1 = p[0];
#pragma unroll
        for (int e = 1; e < EDIM; e++) if (p[e] > p1) { p1 = p[e]; i1 = e; }
        int i2 = -1; float p2 = -1.f;
#pragma unroll
        for (int e = 0; e < EDIM; e++) if (e != i1 && p[e] > p2) { p2 = p[e]; i2 = e; }

        float wsum = p1 + p2 + 1e-9f;
        float w1 = p1 / wsum, w2 = p2 / wsum;

        topk_out[t * 2 + 0] = (float)i1;
        topk_out[t * 2 + 1] = (float)i2;
        g_topk_e[t * 2 + 0] = i1;  g_topk_e[t * 2 + 1] = i2;
        g_topk_w[t * 2 + 0] = w1;  g_topk_w[t * 2 + 1] = w2;
        atomicAdd(&g_counts[i1], 1);
        atomicAdd(&g_counts[i2], 1);
    }
}

// ---------------------------------------------------------------------
__global__ void offsets_kernel() {
    if (threadIdx.x == 0) {
        int off = 0;
#pragma unroll
        for (int e = 0; e < EDIM; e++) { g_offsets[e] = off; off += g_counts[e]; }
    }
}

__global__ void scatter_kernel() {
    int t = blockIdx.x * blockDim.x + threadIdx.x;
    if (t >= TOKENS) return;
#pragma unroll
    for (int k = 0; k < KSEL; k++) {
        int e = g_topk_e[t * 2 + k];
        int pos = atomicAdd(&g_cursor[e], 1);
        int idx = g_offsets[e] + pos;
        g_pair_tok[idx] = t;
        g_pair_w[idx] = g_topk_w[t * 2 + k];
    }
}

// ---------------------------------------------------------------------
// GEMM machinery: 128x128 tile, BK=16, 8x8 per thread, NT layout,
// double-buffered smem with register-staged prefetch.
// Inner math uses PACKED fp32 FMA (fma.rn.f32x2): 3-reg FFMA has
// rt_SMSP=2 on sm_103a (64 FMA/cyc/SM); FFMA2 restores 128 FMA/cyc/SM.
// Accumulators: c2[i][jp] = packed (j=2*jp, j=2*jp+1) fp32 pair.
// ---------------------------------------------------------------------
#define FMA2(acc, a2, b2) \
    asm("fma.rn.f32x2 %0, %1, %2, %0;" : "+l"(acc) : "l"(a2), "l"(b2))

#define STORE_TILE(As, Bs, kb, row) do {                                   \
    As[(kb + 0) * 128 + row] = av0.x;  As[(kb + 1) * 128 + row] = av0.y;   \
    As[(kb + 2) * 128 + row] = av0.z;  As[(kb + 3) * 128 + row] = av0.w;   \
    As[(kb + 4) * 128 + row] = av1.x;  As[(kb + 5) * 128 + row] = av1.y;   \
    As[(kb + 6) * 128 + row] = av1.z;  As[(kb + 7) * 128 + row] = av1.w;   \
    Bs[(kb + 0) * 128 + row] = bv0.x;  Bs[(kb + 1) * 128 + row] = bv0.y;   \
    Bs[(kb + 2) * 128 + row] = bv0.z;  Bs[(kb + 3) * 128 + row] = bv0.w;   \
    Bs[(kb + 4) * 128 + row] = bv1.x;  Bs[(kb + 5) * 128 + row] = bv1.y;   \
    Bs[(kb + 6) * 128 + row] = bv1.z;  Bs[(kb + 7) * 128 + row] = bv1.w;   \
} while (0)

#define COMPUTE_TILE2(As, Bs) do {                                         \
    _Pragma("unroll")                                                      \
    for (int kk = 0; kk < 16; kk++) {                                      \
        const ulonglong2* bq =                                             \
            (const ulonglong2*)(Bs + kk * 128 + tx * 8);                   \
        ulonglong2 blo = bq[0];                                            \
        ulonglong2 bhi = bq[1];                                            \
        const uint4* aq = (const uint4*)(As + kk * 128 + ty * 8);          \
        uint4 au0 = aq[0];                                                 \
        uint4 au1 = aq[1];                                                 \
        unsigned ar[8] = {au0.x, au0.y, au0.z, au0.w,                      \
                          au1.x, au1.y, au1.z, au1.w};                     \
        _Pragma("unroll")                                                  \
        for (int i = 0; i < 8; i++) {                                      \
            uint64_t aa;                                                   \
            asm("mov.b64 %0, {%1, %1};" : "=l"(aa) : "r"(ar[i]));          \
            FMA2(c2[i][0], aa, blo.x);                                     \
            FMA2(c2[i][1], aa, blo.y);                                     \
            FMA2(c2[i][2], aa, bhi.x);                                     \
            FMA2(c2[i][3], aa, bhi.y);                                     \
        }                                                                  \
    }                                                                      \
} while (0)

#define UNPACK2(lo, hi, v) \
    asm("mov.b64 {%0, %1}, %2;" : "=r"(lo), "=r"(hi) : "l"(v))

// ---------------------------------------------------------------------
// GEMM1: act[p, f] = GELU( x[tok(p), :] . fc1_w[e, f, :] + fc1_b[e, f] )
// grid: (FDIM/128, TOKENS/128, EDIM); empty tiles early-exit.
// ---------------------------------------------------------------------
__global__ __launch_bounds__(256, 2)
void gemm1_kernel(const float* __restrict__ x,
                  const float* __restrict__ fc1_w,
                  const float* __restrict__ fc1_b) {
    const int e = blockIdx.z;
    const int count = g_counts[e];
    const int mt = blockIdx.y;
    if (mt * 128 >= count) return;
    const int base = g_offsets[e];
    const int ft = blockIdx.x;

    __shared__ float As[2][16 * 128];   // 16 KB x2
    __shared__ float Bs[2][16 * 128];   // 16 KB x2

    const int tid = threadIdx.x;
    const int row = tid >> 1;            // 0..127
    const int kb  = (tid & 1) * 8;       // k sub-offset: 0 or 8
    const int tx = tid & 15;             // n-dir
    const int ty = tid >> 4;             // m-dir

    const int m_g = mt * 128 + row;
    const int tok = (m_g < count) ? g_pair_tok[base + m_g] : 0;
    const float* aptr = x + tok * HDIM + kb;
    const float* bptr = fc1_w + (size_t)(e * FDIM + ft * 128 + row) * HDIM + kb;

    uint64_t c2[8][4];
#pragma unroll
    for (int i = 0; i < 8; i++)
#pragma unroll
        for (int j = 0; j < 4; j++) c2[i][j] = 0ull;   // packed (+0,+0)

    // prologue: load k-tile 0
    float4 av0 = *(const float4*)(aptr);
    float4 av1 = *(const float4*)(aptr + 4);
    float4 bv0 = *(const float4*)(bptr);
    float4 bv1 = *(const float4*)(bptr + 4);

    int buf = 0;
    for (int k0 = 0; k0 < HDIM; k0 += 16) {
        STORE_TILE(As[buf], Bs[buf], kb, row);
        __syncthreads();
        if (k0 + 16 < HDIM) {           // prefetch next k-tile (overlaps compute)
            av0 = *(const float4*)(aptr + k0 + 16);
            av1 = *(const float4*)(aptr + k0 + 20);
            bv0 = *(const float4*)(bptr + k0 + 16);
            bv1 = *(const float4*)(bptr + k0 + 20);
        }
        COMPUTE_TILE2(As[buf], Bs[buf]);
        buf ^= 1;
    }

    const int fbase = ft * 128 + tx * 8;
    // hoist bias row (8 contiguous floats) once
    float bias[8];
#pragma unroll
    for (int j = 0; j < 8; j++) bias[j] = fc1_b[e * FDIM + fbase + j];

#pragma unroll
    for (int i = 0; i < 8; i++) {
        int m = mt * 128 + ty * 8 + i;
        if (m >= count) continue;
        float* dst = g_act + (size_t)(base + m) * FDIM + fbase;
#pragma unroll
        for (int jp = 0; jp < 4; jp++) {
            unsigned u0, u1;
            UNPACK2(u0, u1, c2[i][jp]);
            float v0 = __uint_as_float(u0) + bias[2 * jp];
            float v1 = __uint_as_float(u1) + bias[2 * jp + 1];
            v0 = 0.5f * v0 * (1.0f + erff(v0 * 0.70710678118654752440f));  // exact GELU
            v1 = 0.5f * v1 * (1.0f + erff(v1 * 0.70710678118654752440f));
            dst[2 * jp]     = v0;
            dst[2 * jp + 1] = v1;
        }
    }
}

// ---------------------------------------------------------------------
// GEMM2: out[tok, h] += w * ( act[p, :] . fc2_w[e, h, :] + fc2_b[e, h] )
// grid: (HDIM/128, TOKENS/128, EDIM)
// ---------------------------------------------------------------------
__global__ __launch_bounds__(256, 2)
void gemm2_kernel(const float* __restrict__ fc2_w,
                  const float* __restrict__ fc2_b,
                  float* __restrict__ out) {
    const int e = blockIdx.z;
    const int count = g_counts[e];
    const int mt = blockIdx.y;
    if (mt * 128 >= count) return;
    const int base = g_offsets[e];
    const int ht = blockIdx.x;

    __shared__ float As[2][16 * 128];
    __shared__ float Bs[2][16 * 128];

    const int tid = threadIdx.x;
    const int row = tid >> 1;
    const int kb  = (tid & 1) * 8;
    const int tx = tid & 15;
    const int ty = tid >> 4;

    const int m_g = mt * 128 + row;
    const int pa = (m_g < count) ? (base + m_g) : base;   // clamp: avoid OOB on g_act
    const float* aptr = g_act + (size_t)pa * FDIM + kb;
    const float* bptr = fc2_w + (size_t)(e * HDIM + ht * 128 + row) * FDIM + kb;

    uint64_t c2[8][4];
#pragma unroll
    for (int i = 0; i < 8; i++)
#pragma unroll
        for (int j = 0; j < 4; j++) c2[i][j] = 0ull;

    float4 av0 = *(const float4*)(aptr);
    float4 av1 = *(const float4*)(aptr + 4);
    float4 bv0 = *(const float4*)(bptr);
    float4 bv1 = *(const float4*)(bptr + 4);

    int buf = 0;
    for (int k0 = 0; k0 < FDIM; k0 += 16) {
        STORE_TILE(As[buf], Bs[buf], kb, row);
        __syncthreads();
        if (k0 + 16 < FDIM) {
            av0 = *(const float4*)(aptr + k0 + 16);
            av1 = *(const float4*)(aptr + k0 + 20);
            bv0 = *(const float4*)(bptr + k0 + 16);
            bv1 = *(const float4*)(bptr + k0 + 20);
        }
        COMPUTE_TILE2(As[buf], Bs[buf]);
        buf ^= 1;
    }

    const int hbase = ht * 128 + tx * 8;
    float bias[8];
#pragma unroll
    for (int j = 0; j < 8; j++) bias[j] = fc2_b[e * HDIM + hbase + j];

#pragma unroll
    for (int i = 0; i < 8; i++) {
        int m = mt * 128 + ty * 8 + i;
        if (m >= count) continue;
        int p = base + m;
        int tok = g_pair_tok[p];
        float w = g_pair_w[p];
        float* dst = out + tok * HDIM + hbase;
#pragma unroll
        for (int jp = 0; jp < 4; jp++) {
            unsigned u0, u1;
            UNPACK2(u0, u1, c2[i][jp]);
            float y0 = __uint_as_float(u0) + bias[2 * jp];
            float y1 = __uint_as_float(u1) + bias[2 * jp + 1];
            atomicAdd(&dst[2 * jp],     w * y0);   // exactly 2 adds/elem -> deterministic
            atomicAdd(&dst[2 * jp + 1], w * y1);
        }
    }
}

// ---------------------------------------------------------------------
extern "C" void kernel_launch(void* const* d_in, const int* in_sizes, int n_in,
                              void* d_out, int out_size) {
    (void)in_sizes; (void)n_in; (void)out_size;
    const float* x        = (const float*)d_in[0];
    const float* router_w = (const float*)d_in[1];
    const float* fc1_w    = (const float*)d_in[2];
    const float* fc1_b    = (const float*)d_in[3];
    const float* fc2_w    = (const float*)d_in[4];
    const float* fc2_b    = (const float*)d_in[5];

    float* out   = (float*)d_out;                 // [TOKENS, HDIM]
    float* probs = out + TOKENS * HDIM;           // [TOKENS, EDIM]
    float* topk  = probs + TOKENS * EDIM;         // [TOKENS, KSEL] (indices as float)

    zero_kernel<<<1024, 256>>>(out);
    router_kernel<<<TOKENS / 8, 256>>>(x, router_w, probs, topk);
    offsets_kernel<<<1, 32>>>();
    scatter_kernel<<<TOKENS / 256, 256>>>();

    dim3 g1(FDIM / 128, TOKENS / 128, EDIM);      // (16, 64, 8)
    gemm1_kernel<<<g1, 256>>>(x, fc1_w, fc1_b);

    dim3 g2(HDIM / 128, TOKENS / 128, EDIM);      // (4, 64, 8)
    gemm2_kernel<<<g2, 256>>>(fc2_w, fc2_b, out);
}

// round 10
// speedup vs baseline: 1.8096x; 1.8078x over previous
#include <cuda_runtime.h>
#include <cuda_bf16.h>
#include <math.h>
#include <stdint.h>

// Problem constants
#define TOKENS   8192
#define HDIM     512
#define FDIM     2048
#define EDIM     8
#define KSEL     2
#define NPAIRS   (TOKENS*KSEL)

// ----- scratch (device globals) -----
__device__ int   g_counts[EDIM];
__device__ int   g_offsets[EDIM];
__device__ int   g_cursor[EDIM];
__device__ int   g_pair_tok[NPAIRS];
__device__ float g_pair_w[NPAIRS];
__device__ int   g_topk_e[NPAIRS];
__device__ float g_topk_w[NPAIRS];
__device__ float g_act[(size_t)NPAIRS * FDIM];   // 128 MB fp32 activations

// =====================================================================
// mma.sync (base-target HMMA) helpers — NO tcgen05 (ptxas targets sm_103
// base, which rejects arch-specific 'a' instructions).
// =====================================================================
__device__ __forceinline__ uint32_t smem_u32(const void* p) {
    uint32_t a;
    asm("{ .reg .u64 t; cvta.to.shared.u64 t, %1; cvt.u32.u64 %0, t; }" : "=r"(a) : "l"(p));
    return a;
}

#define MMA_BF16(d, a, b)                                                     \
    asm volatile(                                                             \
        "mma.sync.aligned.m16n8k16.row.col.f32.bf16.bf16.f32 "                \
        "{%0,%1,%2,%3}, {%4,%5,%6,%7}, {%8,%9}, {%0,%1,%2,%3};"               \
        : "+f"((d)[0]), "+f"((d)[1]), "+f"((d)[2]), "+f"((d)[3])              \
        : "r"((a)[0]), "r"((a)[1]), "r"((a)[2]), "r"((a)[3]),                 \
          "r"((b)[0]), "r"((b)[1]))

#define LDSM_X4(r, addr)                                                      \
    asm volatile("ldmatrix.sync.aligned.m8n8.x4.shared.b16 {%0,%1,%2,%3}, [%4];" \
        : "=r"((r)[0]), "=r"((r)[1]), "=r"((r)[2]), "=r"((r)[3]) : "r"(addr))

#define LDSM_X2(r, addr)                                                      \
    asm volatile("ldmatrix.sync.aligned.m8n8.x2.shared.b16 {%0,%1}, [%2];"    \
        : "=r"((r)[0]), "=r"((r)[1]) : "r"(addr))

#define STS128(r0, r1, r2, r3, addr)                                          \
    asm volatile("st.shared.v4.b32 [%0], {%1, %2, %3, %4};"                   \
        :: "r"(addr), "r"(r0), "r"(r1), "r"(r2), "r"(r3) : "memory")

// split fp32 pair -> bf16x2 hi + bf16x2 lo residual
__device__ __forceinline__ void split2(float x0, float x1, unsigned& h2, unsigned& l2) {
    __nv_bfloat162 h = __floats2bfloat162_rn(x0, x1);
    float r0 = x0 - __bfloat162float(h.x);
    float r1 = x1 - __bfloat162float(h.y);
    __nv_bfloat162 l = __floats2bfloat162_rn(r0, r1);
    h2 = *reinterpret_cast<unsigned*>(&h);
    l2 = *reinterpret_cast<unsigned*>(&l);
}

__device__ __forceinline__ float gelu_exact(float v) {
    return 0.5f * v * (1.0f + erff(v * 0.70710678118654752440f));
}

// smem layout (dynamic): bias 512B, then 2 stages of 4 tiles.
// Tile: 128 rows x 16 bf16, padded row stride 48B (16B-aligned, low conflict).
#define SM_BIAS   0
#define SM_TILES  512
#define TILE_B    (128 * 48)            // 6144
#define STAGE_B   (4 * TILE_B)          // Ahi, Alo, Bhi, Blo = 24576
#define SMEM_TC   (SM_TILES + 2 * STAGE_B)   // 49664

// ---------------------------------------------------------------------
// Mainloop: accumulate acc[4][4][4] (warp tile 64x32) over niter k16 steps.
// arow/brow = this thread's source row pointers (k-contiguous fp32).
// ---------------------------------------------------------------------
__device__ __forceinline__ void tc_mainloop(uint32_t smb,
                                            const float* arow, const float* brow,
                                            int niter, int tid,
                                            float acc[4][4][4]) {
    const int row  = tid >> 1;
    const int h    = tid & 1;
    const int koff = h * 8;
    const int lane = tid & 31;
    const int wid  = tid >> 5;
    const int wm   = (wid >> 2) * 64;     // warp m base (0 / 64)
    const int wn   = (wid & 3) * 32;      // warp n base (0..96)

    const uint32_t sts_off  = (uint32_t)(row * 48 + h * 16);
    const uint32_t a_ld_off = (uint32_t)((lane & 15) * 48 + (lane >> 4) * 16 + wm * 48);
    const uint32_t b_ld_off = (uint32_t)((lane & 7) * 48 + ((lane >> 3) & 1) * 16 + wn * 48);

    // prologue loads
    float4 av0 = *(const float4*)(arow + koff);
    float4 av1 = *(const float4*)(arow + koff + 4);
    float4 bv0 = *(const float4*)(brow + koff);
    float4 bv1 = *(const float4*)(brow + koff + 4);

#pragma unroll 1
    for (int c = 0; c < niter; c++) {
        const uint32_t sb = smb + SM_TILES + (uint32_t)(c & 1) * STAGE_B;
        // split + store current k-tile
        {
            unsigned h0, l0, h1, l1, h2, l2, h3, l3;
            split2(av0.x, av0.y, h0, l0);
            split2(av0.z, av0.w, h1, l1);
            split2(av1.x, av1.y, h2, l2);
            split2(av1.z, av1.w, h3, l3);
            STS128(h0, h1, h2, h3, sb + sts_off);
            STS128(l0, l1, l2, l3, sb + TILE_B + sts_off);
            split2(bv0.x, bv0.y, h0, l0);
            split2(bv0.z, bv0.w, h1, l1);
            split2(bv1.x, bv1.y, h2, l2);
            split2(bv1.z, bv1.w, h3, l3);
            STS128(h0, h1, h2, h3, sb + 2 * TILE_B + sts_off);
            STS128(l0, l1, l2, l3, sb + 3 * TILE_B + sts_off);
        }
        __syncthreads();
        if (c + 1 < niter) {   // prefetch next k-tile (overlaps compute)
            const float* ap = arow + (c + 1) * 16 + koff;
            const float* bp = brow + (c + 1) * 16 + koff;
            av0 = *(const float4*)(ap);
            av1 = *(const float4*)(ap + 4);
            bv0 = *(const float4*)(bp);
            bv1 = *(const float4*)(bp + 4);
        }
        // load fragments
        unsigned ah[4][4], al[4][4], bh[4][2], bl[4][2];
#pragma unroll
        for (int mi = 0; mi < 4; mi++) {
            LDSM_X4(ah[mi], sb + a_ld_off + (uint32_t)(mi * 16 * 48));
            LDSM_X4(al[mi], sb + TILE_B + a_ld_off + (uint32_t)(mi * 16 * 48));
        }
#pragma unroll
        for (int ni = 0; ni < 4; ni++) {
            LDSM_X2(bh[ni], sb + 2 * TILE_B + b_ld_off + (uint32_t)(ni * 8 * 48));
            LDSM_X2(bl[ni], sb + 3 * TILE_B + b_ld_off + (uint32_t)(ni * 8 * 48));
        }
        // 3-term split MMA
#pragma unroll
        for (int mi = 0; mi < 4; mi++)
#pragma unroll
            for (int ni = 0; ni < 4; ni++) {
                MMA_BF16(acc[mi][ni], ah[mi], bh[ni]);
                MMA_BF16(acc[mi][ni], ah[mi], bl[ni]);
                MMA_BF16(acc[mi][ni], al[mi], bh[ni]);
            }
    }
    __syncthreads();
}

// ---------------------------------------------------------------------
// GEMM1 (HMMA): act[p, f] = GELU(x[tok(p),:] . fc1_w[e,f,:] + b)
// grid (FDIM/128, TOKENS/128, EDIM), 256 threads
// ---------------------------------------------------------------------
__global__ __launch_bounds__(256, 1)
void gemm1_tc(const float* __restrict__ x,
              const float* __restrict__ fc1_w,
              const float* __restrict__ fc1_b) {
    extern __shared__ char dsm[];
    const int e = blockIdx.z;
    const int count = g_counts[e];
    const int mt = blockIdx.y;
    if (mt * 128 >= count) return;
    const int base = g_offsets[e];
    const int ft = blockIdx.x;

    const uint32_t smb = smem_u32(dsm);
    const int tid = threadIdx.x, lane = tid & 31, wid = tid >> 5;
    const int row = tid >> 1;

    if (tid < 128) ((float*)(dsm + SM_BIAS))[tid] = fc1_b[e * FDIM + ft * 128 + tid];
    __syncthreads();

    const int m = mt * 128 + row;
    const int tok = (m < count) ? g_pair_tok[base + m] : g_pair_tok[base];
    const float* arow = x + (size_t)tok * HDIM;
    const float* brow = fc1_w + ((size_t)e * FDIM + ft * 128 + row) * HDIM;

    float acc[4][4][4];
#pragma unroll
    for (int i = 0; i < 4; i++)
#pragma unroll
        for (int j = 0; j < 4; j++)
#pragma unroll
            for (int k = 0; k < 4; k++) acc[i][j][k] = 0.f;

    tc_mainloop(smb, arow, brow, HDIM / 16, tid, acc);

    // epilogue: c-frag rows (t>>2)+{0,8}, cols 2*(t&3)+{0,1}
    const float* bias = (const float*)(dsm + SM_BIAS);
    const int wm = (wid >> 2) * 64, wn = (wid & 3) * 32;
#pragma unroll
    for (int mi = 0; mi < 4; mi++) {
#pragma unroll
        for (int hf = 0; hf < 2; hf++) {
            const int ml = wm + mi * 16 + (lane >> 2) + hf * 8;
            const int mg = mt * 128 + ml;
            if (mg >= count) continue;
            float* dstrow = g_act + (size_t)(base + mg) * FDIM + ft * 128;
#pragma unroll
            for (int ni = 0; ni < 4; ni++) {
                const int n = wn + ni * 8 + (lane & 3) * 2;
                float v0 = gelu_exact(acc[mi][ni][hf * 2 + 0] + bias[n]);
                float v1 = gelu_exact(acc[mi][ni][hf * 2 + 1] + bias[n + 1]);
                *(float2*)(dstrow + n) = make_float2(v0, v1);
            }
        }
    }
}

// ---------------------------------------------------------------------
// GEMM2 (HMMA): out[tok,h] += w * (act[p,:] . fc2_w[e,h,:] + b)
// grid (HDIM/128, TOKENS/128, EDIM)
// ---------------------------------------------------------------------
__global__ __launch_bounds__(256, 1)
void gemm2_tc(const float* __restrict__ fc2_w,
              const float* __restrict__ fc2_b,
              float* __restrict__ out) {
    extern __shared__ char dsm[];
    const int e = blockIdx.z;
    const int count = g_counts[e];
    const int mt = blockIdx.y;
    if (mt * 128 >= count) return;
    const int base = g_offsets[e];
    const int ht = blockIdx.x;

    const uint32_t smb = smem_u32(dsm);
    const int tid = threadIdx.x, lane = tid & 31, wid = tid >> 5;
    const int row = tid >> 1;

    if (tid < 128) ((float*)(dsm + SM_BIAS))[tid] = fc2_b[e * HDIM + ht * 128 + tid];
    __syncthreads();

    const int m = mt * 128 + row;
    const int pa = base + ((m < count) ? m : (count - 1));
    const float* arow = g_act + (size_t)pa * FDIM;
    const float* brow = fc2_w + ((size_t)e * HDIM + ht * 128 + row) * FDIM;

    float acc[4][4][4];
#pragma unroll
    for (int i = 0; i < 4; i++)
#pragma unroll
        for (int j = 0; j < 4; j++)
#pragma unroll
            for (int k = 0; k < 4; k++) acc[i][j][k] = 0.f;

    tc_mainloop(smb, arow, brow, FDIM / 16, tid, acc);

    const float* bias = (const float*)(dsm + SM_BIAS);
    const int wm = (wid >> 2) * 64, wn = (wid & 3) * 32;
#pragma unroll
    for (int mi = 0; mi < 4; mi++) {
#pragma unroll
        for (int hf = 0; hf < 2; hf++) {
            const int ml = wm + mi * 16 + (lane >> 2) + hf * 8;
            const int mg = mt * 128 + ml;
            if (mg >= count) continue;
            const int p = base + mg;
            const int tok = g_pair_tok[p];
            const float w = g_pair_w[p];
            float* dstrow = out + (size_t)tok * HDIM + ht * 128;
#pragma unroll
            for (int ni = 0; ni < 4; ni++) {
                const int n = wn + ni * 8 + (lane & 3) * 2;
                float y0 = acc[mi][ni][hf * 2 + 0] + bias[n];
                float y1 = acc[mi][ni][hf * 2 + 1] + bias[n + 1];
                atomicAdd(dstrow + n,     w * y0);   // 2 adds/elem, commutative
                atomicAdd(dstrow + n + 1, w * y1);
            }
        }
    }
}

// ---------------------------------------------------------------------
// Pre/post kernels (unchanged from passing baseline)
// ---------------------------------------------------------------------
__global__ void zero_kernel(float* __restrict__ out) {
    int i = blockIdx.x * blockDim.x + threadIdx.x;
    float4* o4 = (float4*)out;
    const int n4 = TOKENS * HDIM / 4;
    float4 z = make_float4(0.f, 0.f, 0.f, 0.f);
    for (int j = i; j < n4; j += gridDim.x * blockDim.x) o4[j] = z;
    if (blockIdx.x == 0 && threadIdx.x < EDIM) {
        g_counts[threadIdx.x] = 0;
        g_cursor[threadIdx.x] = 0;
    }
}

__global__ void router_kernel(const float* __restrict__ x,
                              const float* __restrict__ rw,
                              float* __restrict__ probs_out,
                              float* __restrict__ topk_out) {
    __shared__ float s_rw[EDIM * HDIM];
    for (int i = threadIdx.x; i < EDIM * HDIM; i += blockDim.x) s_rw[i] = rw[i];
    __syncthreads();

    const int warp = threadIdx.x >> 5;
    const int lane = threadIdx.x & 31;
    const int t = blockIdx.x * 8 + warp;
    if (t >= TOKENS) return;

    const float* xr = x + t * HDIM;
    float acc[EDIM];
#pragma unroll
    for (int e = 0; e < EDIM; e++) acc[e] = 0.f;
    for (int h = lane; h < HDIM; h += 32) {
        float v = xr[h];
#pragma unroll
        for (int e = 0; e < EDIM; e++) acc[e] = fmaf(v, s_rw[e * HDIM + h], acc[e]);
    }
#pragma unroll
    for (int e = 0; e < EDIM; e++) {
#pragma unroll
        for (int off = 16; off > 0; off >>= 1)
            acc[e] += __shfl_xor_sync(0xffffffff, acc[e], off);
    }
    if (lane == 0) {
        float mx = acc[0];
#pragma unroll
        for (int e = 1; e < EDIM; e++) mx = fmaxf(mx, acc[e]);
        float p[EDIM]; float s = 0.f;
#pragma unroll
        for (int e = 0; e < EDIM; e++) { p[e] = expf(acc[e] - mx); s += p[e]; }
        float inv = 1.f / s;
#pragma unroll
        for (int e = 0; e < EDIM; e++) { p[e] *= inv; probs_out[t * EDIM + e] = p[e]; }
        int i1 = 0; float p1 = p[0];
#pragma unroll
        for (int e = 1; e < EDIM; e++) if (p[e] > p1) { p1 = p[e]; i1 = e; }
        int i2 = -1; float p2 = -1.f;
#pragma unroll
        for (int e = 0; e < EDIM; e++) if (e != i1 && p[e] > p2) { p2 = p[e]; i2 = e; }
        float wsum = p1 + p2 + 1e-9f;
        topk_out[t * 2 + 0] = (float)i1;
        topk_out[t * 2 + 1] = (float)i2;
        g_topk_e[t * 2 + 0] = i1;  g_topk_e[t * 2 + 1] = i2;
        g_topk_w[t * 2 + 0] = p1 / wsum;  g_topk_w[t * 2 + 1] = p2 / wsum;
        atomicAdd(&g_counts[i1], 1);
        atomicAdd(&g_counts[i2], 1);
    }
}

__global__ void offsets_kernel() {
    if (threadIdx.x == 0) {
        int off = 0;
#pragma unroll
        for (int e = 0; e < EDIM; e++) { g_offsets[e] = off; off += g_counts[e]; }
    }
}

__global__ void scatter_kernel() {
    int t = blockIdx.x * blockDim.x + threadIdx.x;
    if (t >= TOKENS) return;
#pragma unroll
    for (int k = 0; k < KSEL; k++) {
        int e = g_topk_e[t * 2 + k];
        int pos = atomicAdd(&g_cursor[e], 1);
        int idx = g_offsets[e] + pos;
        g_pair_tok[idx] = t;
        g_pair_w[idx] = g_topk_w[t * 2 + k];
    }
}

// ---------------------------------------------------------------------
extern "C" void kernel_launch(void* const* d_in, const int* in_sizes, int n_in,
                              void* d_out, int out_size) {
    (void)in_sizes; (void)n_in; (void)out_size;
    const float* x        = (const float*)d_in[0];
    const float* router_w = (const float*)d_in[1];
    const float* fc1_w    = (const float*)d_in[2];
    const float* fc1_b    = (const float*)d_in[3];
    const float* fc2_w    = (const float*)d_in[4];
    const float* fc2_b    = (const float*)d_in[5];

    float* out   = (float*)d_out;
    float* probs = out + TOKENS * HDIM;
    float* topk  = probs + TOKENS * EDIM;

    cudaFuncSetAttribute(gemm1_tc, cudaFuncAttributeMaxDynamicSharedMemorySize, SMEM_TC);
    cudaFuncSetAttribute(gemm2_tc, cudaFuncAttributeMaxDynamicSharedMemorySize, SMEM_TC);

    zero_kernel<<<1024, 256>>>(out);
    router_kernel<<<TOKENS / 8, 256>>>(x, router_w, probs, topk);
    offsets_kernel<<<1, 32>>>();
    scatter_kernel<<<TOKENS / 256, 256>>>();

    dim3 g1(FDIM / 128, TOKENS / 128, EDIM);
    gemm1_tc<<<g1, 256, SMEM_TC>>>(x, fc1_w, fc1_b);

    dim3 g2(HDIM / 128, TOKENS / 128, EDIM);
    gemm2_tc<<<g2, 256, SMEM_TC>>>(fc2_w, fc2_b, out);
}

// round 12
// speedup vs baseline: 1.8631x; 1.0296x over previous
#include <cuda_runtime.h>
#include <cuda_bf16.h>
#include <math.h>
#include <stdint.h>

// Problem constants
#define TOKENS   8192
#define HDIM     512
#define FDIM     2048
#define EDIM     8
#define KSEL     2
#define NPAIRS   (TOKENS*KSEL)
#define W1SZ     (EDIM*FDIM*HDIM)      // 8388608
#define W2SZ     (EDIM*HDIM*FDIM)      // 8388608
#define ACTSZ    ((size_t)NPAIRS*FDIM) // 33554432

// ----- scratch (device globals) -----
__device__ int   g_counts[EDIM];
__device__ int   g_offsets[EDIM];
__device__ int   g_cursor[EDIM];
__device__ int   g_pair_tok[NPAIRS];
__device__ float g_pair_w[NPAIRS];
__device__ int   g_topk_e[NPAIRS];
__device__ float g_topk_w[NPAIRS];
// bf16 hi/lo planes: weights (precomputed per launch) + activations
__device__ __nv_bfloat16 g_w1h[W1SZ], g_w1l[W1SZ];
__device__ __nv_bfloat16 g_w2h[W2SZ], g_w2l[W2SZ];
__device__ __nv_bfloat16 g_acth[ACTSZ], g_actl[ACTSZ];

// =====================================================================
// mma.sync (base-target HMMA) helpers — NO tcgen05 (ptxas targets sm_103
// base, which rejects arch-specific 'a' instructions).
// =====================================================================
__device__ __forceinline__ uint32_t smem_u32(const void* p) {
    uint32_t a;
    asm("{ .reg .u64 t; cvta.to.shared.u64 t, %1; cvt.u32.u64 %0, t; }" : "=r"(a) : "l"(p));
    return a;
}

#define MMA_BF16(d, a, b)                                                     \
    asm volatile(                                                             \
        "mma.sync.aligned.m16n8k16.row.col.f32.bf16.bf16.f32 "                \
        "{%0,%1,%2,%3}, {%4,%5,%6,%7}, {%8,%9}, {%0,%1,%2,%3};"               \
        : "+f"((d)[0]), "+f"((d)[1]), "+f"((d)[2]), "+f"((d)[3])              \
        : "r"((a)[0]), "r"((a)[1]), "r"((a)[2]), "r"((a)[3]),                 \
          "r"((b)[0]), "r"((b)[1]))

#define LDSM_X4(r, addr)                                                      \
    asm volatile("ldmatrix.sync.aligned.m8n8.x4.shared.b16 {%0,%1,%2,%3}, [%4];" \
        : "=r"((r)[0]), "=r"((r)[1]), "=r"((r)[2]), "=r"((r)[3]) : "r"(addr))

#define LDSM_X2(r, addr)                                                      \
    asm volatile("ldmatrix.sync.aligned.m8n8.x2.shared.b16 {%0,%1}, [%2];"    \
        : "=r"((r)[0]), "=r"((r)[1]) : "r"(addr))

#define STS128(r0, r1, r2, r3, addr)                                          \
    asm volatile("st.shared.v4.b32 [%0], {%1, %2, %3, %4};"                   \
        :: "r"(addr), "r"(r0), "r"(r1), "r"(r2), "r"(r3) : "memory")

// split fp32 pair -> bf16x2 hi + bf16x2 lo residual
__device__ __forceinline__ void split2(float x0, float x1, unsigned& h2, unsigned& l2) {
    __nv_bfloat162 h = __floats2bfloat162_rn(x0, x1);
    float r0 = x0 - __bfloat162float(h.x);
    float r1 = x1 - __bfloat162float(h.y);
    __nv_bfloat162 l = __floats2bfloat162_rn(r0, r1);
    h2 = *reinterpret_cast<unsigned*>(&h);
    l2 = *reinterpret_cast<unsigned*>(&l);
}

__device__ __forceinline__ float gelu_exact(float v) {
    return 0.5f * v * (1.0f + erff(v * 0.70710678118654752440f));
}

// smem layout (dynamic): bias 512B, then 2 stages of 4 tiles.
// Tile: 128 rows x 16 bf16, padded row stride 48B.
#define SM_BIAS   0
#define SM_TILES  512
#define TILE_B    (128 * 48)            // 6144
#define STAGE_B   (4 * TILE_B)          // Ahi, Alo, Bhi, Blo = 24576
#define SMEM_TC   (SM_TILES + 2 * STAGE_B)   // 49664

// ---------------------------------------------------------------------
// Weight conversion: fp32 -> bf16 hi/lo planes. Grid-stride over float4s.
// ---------------------------------------------------------------------
__global__ void convert_w_kernel(const float* __restrict__ w1,
                                 const float* __restrict__ w2) {
    const int n4 = W1SZ / 4;
    for (int j = blockIdx.x * blockDim.x + threadIdx.x; j < n4;
         j += gridDim.x * blockDim.x) {
        float4 v = ((const float4*)w1)[j];
        unsigned h0, l0, h1, l1;
        split2(v.x, v.y, h0, l0);
        split2(v.z, v.w, h1, l1);
        ((uint2*)g_w1h)[j] = make_uint2(h0, h1);
        ((uint2*)g_w1l)[j] = make_uint2(l0, l1);
        v = ((const float4*)w2)[j];
        split2(v.x, v.y, h0, l0);
        split2(v.z, v.w, h1, l1);
        ((uint2*)g_w2h)[j] = make_uint2(h0, h1);
        ((uint2*)g_w2l)[j] = make_uint2(l0, l1);
    }
}

// ---------------------------------------------------------------------
// Shared fragment-load + MMA block (identical to measured-passing R10)
// ---------------------------------------------------------------------
#define FRAG_AND_MMA(sb)                                                      \
    do {                                                                      \
        unsigned ah[4][4], al[4][4], bh[4][2], bl[4][2];                      \
        _Pragma("unroll")                                                     \
        for (int mi = 0; mi < 4; mi++) {                                      \
            LDSM_X4(ah[mi], (sb) + a_ld_off + (uint32_t)(mi * 16 * 48));      \
            LDSM_X4(al[mi], (sb) + TILE_B + a_ld_off + (uint32_t)(mi * 16 * 48)); \
        }                                                                     \
        _Pragma("unroll")                                                     \
        for (int ni = 0; ni < 4; ni++) {                                      \
            LDSM_X2(bh[ni], (sb) + 2 * TILE_B + b_ld_off + (uint32_t)(ni * 8 * 48)); \
            LDSM_X2(bl[ni], (sb) + 3 * TILE_B + b_ld_off + (uint32_t)(ni * 8 * 48)); \
        }                                                                     \
        _Pragma("unroll")                                                     \
        for (int mi = 0; mi < 4; mi++)                                        \
            _Pragma("unroll")                                                 \
            for (int ni = 0; ni < 4; ni++) {                                  \
                MMA_BF16(acc[mi][ni], ah[mi], bh[ni]);                        \
                MMA_BF16(acc[mi][ni], ah[mi], bl[ni]);                        \
                MMA_BF16(acc[mi][ni], al[mi], bh[ni]);                        \
            }                                                                 \
    } while (0)

// ---------------------------------------------------------------------
// GEMM1 mainloop: A fp32 (split in kernel), B bf16 hi/lo planes (direct)
// ---------------------------------------------------------------------
__device__ __forceinline__ void mainloop_g1(uint32_t smb, const float* arow,
                                            const __nv_bfloat16* browh,
                                            const __nv_bfloat16* browl,
                                            int niter, int tid,
                                            float acc[4][4][4]) {
    const int row  = tid >> 1;
    const int h    = tid & 1;
    const int koff = h * 8;
    const int lane = tid & 31;
    const int wid  = tid >> 5;
    const int wm   = (wid >> 2) * 64;
    const int wn   = (wid & 3) * 32;

    const uint32_t sts_off  = (uint32_t)(row * 48 + h * 16);
    const uint32_t a_ld_off = (uint32_t)((lane & 15) * 48 + (lane >> 4) * 16 + wm * 48);
    const uint32_t b_ld_off = (uint32_t)((lane & 7) * 48 + ((lane >> 3) & 1) * 16 + wn * 48);

    float4 av0 = *(const float4*)(arow + koff);
    float4 av1 = *(const float4*)(arow + koff + 4);
    uint4  bh4 = *(const uint4*)(browh + koff);
    uint4  bl4 = *(const uint4*)(browl + koff);

#pragma unroll 1
    for (int c = 0; c < niter; c++) {
        const uint32_t sb = smb + SM_TILES + (uint32_t)(c & 1) * STAGE_B;
        {
            unsigned h0, l0, h1, l1, h2, l2, h3, l3;
            split2(av0.x, av0.y, h0, l0);
            split2(av0.z, av0.w, h1, l1);
            split2(av1.x, av1.y, h2, l2);
            split2(av1.z, av1.w, h3, l3);
            STS128(h0, h1, h2, h3, sb + sts_off);
            STS128(l0, l1, l2, l3, sb + TILE_B + sts_off);
            STS128(bh4.x, bh4.y, bh4.z, bh4.w, sb + 2 * TILE_B + sts_off);
            STS128(bl4.x, bl4.y, bl4.z, bl4.w, sb + 3 * TILE_B + sts_off);
        }
        __syncthreads();
        if (c + 1 < niter) {
            const float* ap = arow + (c + 1) * 16 + koff;
            av0 = *(const float4*)(ap);
            av1 = *(const float4*)(ap + 4);
            bh4 = *(const uint4*)(browh + (c + 1) * 16 + koff);
            bl4 = *(const uint4*)(browl + (c + 1) * 16 + koff);
        }
        FRAG_AND_MMA(sb);
    }
    __syncthreads();
}

// ---------------------------------------------------------------------
// GEMM2 mainloop: A and B both bf16 hi/lo planes (no split at all)
// ---------------------------------------------------------------------
__device__ __forceinline__ void mainloop_g2(uint32_t smb,
                                            const __nv_bfloat16* arowh,
                                            const __nv_bfloat16* arowl,
                                            const __nv_bfloat16* browh,
                                            const __nv_bfloat16* browl,
                                            int niter, int tid,
                                            float acc[4][4][4]) {
    const int row  = tid >> 1;
    const int h    = tid & 1;
    const int koff = h * 8;
    const int lane = tid & 31;
    const int wid  = tid >> 5;
    const int wm   = (wid >> 2) * 64;
    const int wn   = (wid & 3) * 32;

    const uint32_t sts_off  = (uint32_t)(row * 48 + h * 16);
    const uint32_t a_ld_off = (uint32_t)((lane & 15) * 48 + (lane >> 4) * 16 + wm * 48);
    const uint32_t b_ld_off = (uint32_t)((lane & 7) * 48 + ((lane >> 3) & 1) * 16 + wn * 48);

    uint4 ah4 = *(const uint4*)(arowh + koff);
    uint4 al4 = *(const uint4*)(arowl + koff);
    uint4 bh4 = *(const uint4*)(browh + koff);
    uint4 bl4 = *(const uint4*)(browl + koff);

#pragma unroll 1
    for (int c = 0; c < niter; c++) {
        const uint32_t sb = smb + SM_TILES + (uint32_t)(c & 1) * STAGE_B;
        STS128(ah4.x, ah4.y, ah4.z, ah4.w, sb + sts_off);
        STS128(al4.x, al4.y, al4.z, al4.w, sb + TILE_B + sts_off);
        STS128(bh4.x, bh4.y, bh4.z, bh4.w, sb + 2 * TILE_B + sts_off);
        STS128(bl4.x, bl4.y, bl4.z, bl4.w, sb + 3 * TILE_B + sts_off);
        __syncthreads();
        if (c + 1 < niter) {
            const int o = (c + 1) * 16 + koff;
            ah4 = *(const uint4*)(arowh + o);
            al4 = *(const uint4*)(arowl + o);
            bh4 = *(const uint4*)(browh + o);
            bl4 = *(const uint4*)(browl + o);
        }
        FRAG_AND_MMA(sb);
    }
    __syncthreads();
}

// ---------------------------------------------------------------------
// GEMM1 (HMMA): act_hi/lo[p, f] = split(GELU(x . fc1_w^T + b))
// grid (FDIM/128, TOKENS/128, EDIM), 256 threads
// ---------------------------------------------------------------------
__global__ __launch_bounds__(256, 1)
void gemm1_tc(const float* __restrict__ x,
              const float* __restrict__ fc1_b) {
    extern __shared__ char dsm[];
    const int e = blockIdx.z;
    const int count = g_counts[e];
    const int mt = blockIdx.y;
    if (mt * 128 >= count) return;
    const int base = g_offsets[e];
    const int ft = blockIdx.x;

    const uint32_t smb = smem_u32(dsm);
    const int tid = threadIdx.x, lane = tid & 31, wid = tid >> 5;
    const int row = tid >> 1;

    if (tid < 128) ((float*)(dsm + SM_BIAS))[tid] = fc1_b[e * FDIM + ft * 128 + tid];
    __syncthreads();

    const int m = mt * 128 + row;
    const int tok = (m < count) ? g_pair_tok[base + m] : g_pair_tok[base];
    const float* arow = x + (size_t)tok * HDIM;
    const size_t wrow = ((size_t)e * FDIM + ft * 128 + row) * HDIM;

    float acc[4][4][4];
#pragma unroll
    for (int i = 0; i < 4; i++)
#pragma unroll
        for (int j = 0; j < 4; j++)
#pragma unroll
            for (int k = 0; k < 4; k++) acc[i][j][k] = 0.f;

    mainloop_g1(smb, arow, g_w1h + wrow, g_w1l + wrow, HDIM / 16, tid, acc);

    const float* bias = (const float*)(dsm + SM_BIAS);
    const int wm = (wid >> 2) * 64, wn = (wid & 3) * 32;
#pragma unroll
    for (int mi = 0; mi < 4; mi++) {
#pragma unroll
        for (int hf = 0; hf < 2; hf++) {
            const int ml = wm + mi * 16 + (lane >> 2) + hf * 8;
            const int mg = mt * 128 + ml;
            if (mg >= count) continue;
            const size_t drow = (size_t)(base + mg) * FDIM + ft * 128;
#pragma unroll
            for (int ni = 0; ni < 4; ni++) {
                const int n = wn + ni * 8 + (lane & 3) * 2;
                float v0 = gelu_exact(acc[mi][ni][hf * 2 + 0] + bias[n]);
                float v1 = gelu_exact(acc[mi][ni][hf * 2 + 1] + bias[n + 1]);
                __nv_bfloat162 hv = __floats2bfloat162_rn(v0, v1);
                float r0 = v0 - __bfloat162float(hv.x);
                float r1 = v1 - __bfloat162float(hv.y);
                __nv_bfloat162 lv = __floats2bfloat162_rn(r0, r1);
                *(__nv_bfloat162*)(g_acth + drow + n) = hv;
                *(__nv_bfloat162*)(g_actl + drow + n) = lv;
            }
        }
    }
}

// ---------------------------------------------------------------------
// GEMM2 (HMMA): out[tok,h] += w * (act . fc2_w^T + b)
// grid (HDIM/128, TOKENS/128, EDIM)
// ---------------------------------------------------------------------
__global__ __launch_bounds__(256, 1)
void gemm2_tc(const float* __restrict__ fc2_b,
              float* __restrict__ out) {
    extern __shared__ char dsm[];
    const int e = blockIdx.z;
    const int count = g_counts[e];
    const int mt = blockIdx.y;
    if (mt * 128 >= count) return;
    const int base = g_offsets[e];
    const int ht = blockIdx.x;

    const uint32_t smb = smem_u32(dsm);
    const int tid = threadIdx.x, lane = tid & 31, wid = tid >> 5;
    const int row = tid >> 1;

    if (tid < 128) ((float*)(dsm + SM_BIAS))[tid] = fc2_b[e * HDIM + ht * 128 + tid];
    __syncthreads();

    const int m = mt * 128 + row;
    const int pa = base + ((m < count) ? m : (count - 1));
    const size_t arow = (size_t)pa * FDIM;
    const size_t wrow = ((size_t)e * HDIM + ht * 128 + row) * FDIM;

    float acc[4][4][4];
#pragma unroll
    for (int i = 0; i < 4; i++)
#pragma unroll
        for (int j = 0; j < 4; j++)
#pragma unroll
            for (int k = 0; k < 4; k++) acc[i][j][k] = 0.f;

    mainloop_g2(smb, g_acth + arow, g_actl + arow,
                g_w2h + wrow, g_w2l + wrow, FDIM / 16, tid, acc);

    const float* bias = (const float*)(dsm + SM_BIAS);
    const int wm = (wid >> 2) * 64, wn = (wid & 3) * 32;
#pragma unroll
    for (int mi = 0; mi < 4; mi++) {
#pragma unroll
        for (int hf = 0; hf < 2; hf++) {
            const int ml = wm + mi * 16 + (lane >> 2) + hf * 8;
            const int mg = mt * 128 + ml;
            if (mg >= count) continue;
            const int p = base + mg;
            const int tok = g_pair_tok[p];
            const float w = g_pair_w[p];
            float* dstrow = out + (size_t)tok * HDIM + ht * 128;
#pragma unroll
            for (int ni = 0; ni < 4; ni++) {
                const int n = wn + ni * 8 + (lane & 3) * 2;
                float y0 = acc[mi][ni][hf * 2 + 0] + bias[n];
                float y1 = acc[mi][ni][hf * 2 + 1] + bias[n + 1];
                atomicAdd(dstrow + n,     w * y0);   // 2 adds/elem, commutative
                atomicAdd(dstrow + n + 1, w * y1);
            }
        }
    }
}

// ---------------------------------------------------------------------
// Pre/post kernels (unchanged from passing baseline)
// ---------------------------------------------------------------------
__global__ void zero_kernel(float* __restrict__ out) {
    int i = blockIdx.x * blockDim.x + threadIdx.x;
    float4* o4 = (float4*)out;
    const int n4 = TOKENS * HDIM / 4;
    float4 z = make_float4(0.f, 0.f, 0.f, 0.f);
    for (int j = i; j < n4; j += gridDim.x * blockDim.x) o4[j] = z;
    if (blockIdx.x == 0 && threadIdx.x < EDIM) {
        g_counts[threadIdx.x] = 0;
        g_cursor[threadIdx.x] = 0;
    }
}

__global__ void router_kernel(const float* __restrict__ x,
                              const float* __restrict__ rw,
                              float* __restrict__ probs_out,
                              float* __restrict__ topk_out) {
    __shared__ float s_rw[EDIM * HDIM];
    for (int i = threadIdx.x; i < EDIM * HDIM; i += blockDim.x) s_rw[i] = rw[i];
    __syncthreads();

    const int warp = threadIdx.x >> 5;
    const int lane = threadIdx.x & 31;
    const int t = blockIdx.x * 8 + warp;
    if (t >= TOKENS) return;

    const float* xr = x + t * HDIM;
    float acc[EDIM];
#pragma unroll
    for (int e = 0; e < EDIM; e++) acc[e] = 0.f;
    for (int h = lane; h < HDIM; h += 32) {
        float v = xr[h];
#pragma unroll
        for (int e = 0; e < EDIM; e++) acc[e] = fmaf(v, s_rw[e * HDIM + h], acc[e]);
    }
#pragma unroll
    for (int e = 0; e < EDIM; e++) {
#pragma unroll
        for (int off = 16; off > 0; off >>= 1)
            acc[e] += __shfl_xor_sync(0xffffffff, acc[e], off);
    }
    if (lane == 0) {
        float mx = acc[0];
#pragma unroll
        for (int e = 1; e < EDIM; e++) mx = fmaxf(mx, acc[e]);
        float p[EDIM]; float s = 0.f;
#pragma unroll
        for (int e = 0; e < EDIM; e++) { p[e] = expf(acc[e] - mx); s += p[e]; }
        float inv = 1.f / s;
#pragma unroll
        for (int e = 0; e < EDIM; e++) { p[e] *= inv; probs_out[t * EDIM + e] = p[e]; }
        int i1 = 0; float p1 = p[0];
#pragma unroll
        for (int e = 1; e < EDIM; e++) if (p[e] > p1) { p1 = p[e]; i1 = e; }
        int i2 = -1; float p2 = -1.f;
#pragma unroll
        for (int e = 0; e < EDIM; e++) if (e != i1 && p[e] > p2) { p2 = p[e]; i2 = e; }
        float wsum = p1 + p2 + 1e-9f;
        topk_out[t * 2 + 0] = (float)i1;
        topk_out[t * 2 + 1] = (float)i2;
        g_topk_e[t * 2 + 0] = i1;  g_topk_e[t * 2 + 1] = i2;
        g_topk_w[t * 2 + 0] = p1 / wsum;  g_topk_w[t * 2 + 1] = p2 / wsum;
        atomicAdd(&g_counts[i1], 1);
        atomicAdd(&g_counts[i2], 1);
    }
}

__global__ void offsets_kernel() {
    if (threadIdx.x == 0) {
        int off = 0;
#pragma unroll
        for (int e = 0; e < EDIM; e++) { g_offsets[e] = off; off += g_counts[e]; }
    }
}

__global__ void scatter_kernel() {
    int t = blockIdx.x * blockDim.x + threadIdx.x;
    if (t >= TOKENS) return;
#pragma unroll
    for (int k = 0; k < KSEL; k++) {
        int e = g_topk_e[t * 2 + k];
        int pos = atomicAdd(&g_cursor[e], 1);
        int idx = g_offsets[e] + pos;
        g_pair_tok[idx] = t;
        g_pair_w[idx] = g_topk_w[t * 2 + k];
    }
}

// ---------------------------------------------------------------------
extern "C" void kernel_launch(void* const* d_in, const int* in_sizes, int n_in,
                              void* d_out, int out_size) {
    (void)in_sizes; (void)n_in; (void)out_size;
    const float* x        = (const float*)d_in[0];
    const float* router_w = (const float*)d_in[1];
    const float* fc1_w    = (const float*)d_in[2];
    const float* fc1_b    = (const float*)d_in[3];
    const float* fc2_w    = (const float*)d_in[4];
    const float* fc2_b    = (const float*)d_in[5];

    float* out   = (float*)d_out;
    float* probs = out + TOKENS * HDIM;
    float* topk  = probs + TOKENS * EDIM;

    cudaFuncSetAttribute(gemm1_tc, cudaFuncAttributeMaxDynamicSharedMemorySize, SMEM_TC);
    cudaFuncSetAttribute(gemm2_tc, cudaFuncAttributeMaxDynamicSharedMemorySize, SMEM_TC);

    zero_kernel<<<1024, 256>>>(out);
    convert_w_kernel<<<2048, 256>>>(fc1_w, fc2_w);
    router_kernel<<<TOKENS / 8, 256>>>(x, router_w, probs, topk);
    offsets_kernel<<<1, 32>>>();
    scatter_kernel<<<TOKENS / 256, 256>>>();

    dim3 g1(FDIM / 128, TOKENS / 128, EDIM);
    gemm1_tc<<<g1, 256, SMEM_TC>>>(x, fc1_b);

    dim3 g2(HDIM / 128, TOKENS / 128, EDIM);
    gemm2_tc<<<g2, 256, SMEM_TC>>>(fc2_b, out);
}